// round 2
// baseline (speedup 1.0000x reference)
#include <cuda_runtime.h>

#define BB  2
#define NN  1024
#define KK  48
#define HH  128
#define CATD 384
#define FFD 512
#define BN  (BB*NN)

// scratch: h_V after node-message + LN1
__device__ float g_hV1[BN*HH];
// E_idx dtype flag: 1 if int64, 0 if int32
__device__ int g_idx64;

__device__ __forceinline__ float gelu_exact(float x) {
    return 0.5f * x * (1.0f + erff(x * 0.70710678118654752f));
}

// Detect whether E_idx is int64 (odd int32 words of first 48 entries all zero)
__global__ void detect_idx_kernel(const int* __restrict__ e32) {
    int all0 = 1;
    #pragma unroll
    for (int i = 1; i < 96; i += 2) all0 &= (e32[i] == 0);
    g_idx64 = all0;
}

__device__ __forceinline__ int load_nbidx(const void* Eidx, int is64, long long pos) {
    int v;
    if (is64) v = (int)((const long long*)Eidx)[pos];
    else      v = ((const int*)Eidx)[pos];
    v = v < 0 ? 0 : (v >= NN ? NN - 1 : v);
    return v;
}

// Register-blocked GEMM tile: this thread's 12 rows x 2 adjacent cols.
// A in smem (broadcast reads), W [KD,128] row-major in global (float2 coalesced).
template<int KD, int LDA>
__device__ __forceinline__ void tile_gemm(const float* sAbase,
                                          const float* __restrict__ W,
                                          int j0, float acc[12][2]) {
    #pragma unroll 4
    for (int i = 0; i < KD; i++) {
        float2 w = *reinterpret_cast<const float2*>(W + i * HH + j0);
        #pragma unroll
        for (int r = 0; r < 12; r++) {
            float a = sAbase[r * LDA + i];
            acc[r][0] = fmaf(a, w.x, acc[r][0]);
            acc[r][1] = fmaf(a, w.y, acc[r][1]);
        }
    }
}

// smem layout for msg kernel
#define S_A   0                       // [48][384]
#define S_X1  (KK*CATD)               // [48][128]
#define S_X2  (S_X1 + KK*HH)          // [48][128]
#define S_P   (S_X2 + KK*HH)          // [4][128] partials + 2 stats
#define SMEM_MSG_FLOATS (S_P + 4*HH + 8)
#define SMEM_MSG_BYTES  (SMEM_MSG_FLOATS * 4)

// EDGE=false: node message -> dh sum -> LN1(h_V+dh) -> g_hV1
// EDGE=true : edge message -> LN3(h_E+me) -> out
template<bool EDGE>
__global__ void __launch_bounds__(256, 1)
msg_kernel(const float* __restrict__ hVsrc,
           const float* __restrict__ hE,
           const void* __restrict__ Eidx,
           const float* __restrict__ maskA,
           const float* __restrict__ Wa, const float* __restrict__ ba,
           const float* __restrict__ Wb, const float* __restrict__ bb,
           const float* __restrict__ Wc, const float* __restrict__ bc,
           const float* __restrict__ lng, const float* __restrict__ lnb,
           float* __restrict__ out)
{
    extern __shared__ float sm[];
    float* sA  = sm + S_A;
    float* sX1 = sm + S_X1;
    float* sX2 = sm + S_X2;
    float* sP  = sm + S_P;

    const int tid = threadIdx.x;
    const int bn  = blockIdx.x;
    const int b   = bn / NN;
    const int is64 = g_idx64;

    const float* center = hVsrc + (size_t)bn * HH;
    const float* hErow  = hE + (size_t)bn * KK * HH;

    // build hEV = [center | h_E | neighbor] for 48 rows
    for (int idx = tid; idx < KK * HH; idx += 256) {
        int r = idx >> 7;
        int j = idx & 127;
        int nb = load_nbidx(Eidx, is64, (long long)bn * KK + r);
        float c = center[j];
        sA[r * CATD + j]        = c;
        sA[r * CATD + 128 + j]  = hErow[r * HH + j];
        sA[r * CATD + 256 + j]  = hVsrc[((size_t)b * NN + nb) * HH + j];
    }
    __syncthreads();

    const int q    = tid >> 6;          // row quarter 0..3
    const int j0   = (tid & 63) * 2;    // adjacent column pair
    const int row0 = q * 12;
    float acc[12][2];

    // ---- GEMM1: [48,384]x[384,128] + gelu ----
    #pragma unroll
    for (int r = 0; r < 12; r++) { acc[r][0] = ba[j0]; acc[r][1] = ba[j0 + 1]; }
    tile_gemm<CATD, CATD>(sA + row0 * CATD, Wa, j0, acc);
    #pragma unroll
    for (int r = 0; r < 12; r++) {
        float2 g = make_float2(gelu_exact(acc[r][0]), gelu_exact(acc[r][1]));
        *reinterpret_cast<float2*>(sX1 + (row0 + r) * HH + j0) = g;
    }
    __syncthreads();

    // ---- GEMM2: [48,128]x[128,128] + gelu ----
    #pragma unroll
    for (int r = 0; r < 12; r++) { acc[r][0] = bb[j0]; acc[r][1] = bb[j0 + 1]; }
    tile_gemm<HH, HH>(sX1 + row0 * HH, Wb, j0, acc);
    #pragma unroll
    for (int r = 0; r < 12; r++) {
        float2 g = make_float2(gelu_exact(acc[r][0]), gelu_exact(acc[r][1]));
        *reinterpret_cast<float2*>(sX2 + (row0 + r) * HH + j0) = g;
    }
    __syncthreads();

    // ---- GEMM3: [48,128]x[128,128] ----
    #pragma unroll
    for (int r = 0; r < 12; r++) { acc[r][0] = bc[j0]; acc[r][1] = bc[j0 + 1]; }
    tile_gemm<HH, HH>(sX2 + row0 * HH, Wc, j0, acc);

    if (!EDGE) {
        // masked sum over this thread's 12 rows
        float s0 = 0.f, s1 = 0.f;
        #pragma unroll
        for (int r = 0; r < 12; r++) {
            float mk = maskA[(size_t)bn * KK + row0 + r];
            s0 = fmaf(mk, acc[r][0], s0);
            s1 = fmaf(mk, acc[r][1], s1);
        }
        sP[q * HH + j0]     = s0;
        sP[q * HH + j0 + 1] = s1;
        __syncthreads();

        // dh + residual, per column
        if (tid < HH) {
            float dh = (sP[tid] + sP[HH + tid] + sP[2 * HH + tid] + sP[3 * HH + tid]) * (1.0f / 48.0f);
            float v = center[tid] + dh;
            sP[tid] = v;   // safe: each thread only rewrites its own slot
        }
        __syncthreads();
        if (tid < 32) {
            float v0 = sP[tid], v1 = sP[tid + 32], v2 = sP[tid + 64], v3 = sP[tid + 96];
            float s  = v0 + v1 + v2 + v3;
            float ss = v0 * v0 + v1 * v1 + v2 * v2 + v3 * v3;
            #pragma unroll
            for (int o = 16; o; o >>= 1) {
                s  += __shfl_xor_sync(0xffffffffu, s, o);
                ss += __shfl_xor_sync(0xffffffffu, ss, o);
            }
            float mean = s * (1.0f / 128.0f);
            float var  = ss * (1.0f / 128.0f) - mean * mean;
            if (tid == 0) { sP[4 * HH] = mean; sP[4 * HH + 1] = rsqrtf(var + 1e-5f); }
        }
        __syncthreads();
        if (tid < HH) {
            float mean = sP[4 * HH], rstd = sP[4 * HH + 1];
            float v = sP[tid];
            g_hV1[(size_t)bn * HH + tid] = (v - mean) * rstd * lng[tid] + lnb[tid];
        }
    } else {
        // residual h_E + me into sX1, then per-row LN3
        #pragma unroll
        for (int r = 0; r < 12; r++) {
            int rr = row0 + r;
            sX1[rr * HH + j0]     = acc[r][0] + hErow[rr * HH + j0];
            sX1[rr * HH + j0 + 1] = acc[r][1] + hErow[rr * HH + j0 + 1];
        }
        __syncthreads();
        int w = tid >> 5, lane = tid & 31;
        for (int r = w; r < KK; r += 8) {
            float v[4];
            #pragma unroll
            for (int u = 0; u < 4; u++) v[u] = sX1[r * HH + lane + 32 * u];
            float s  = v[0] + v[1] + v[2] + v[3];
            float ss = v[0]*v[0] + v[1]*v[1] + v[2]*v[2] + v[3]*v[3];
            #pragma unroll
            for (int o = 16; o; o >>= 1) {
                s  += __shfl_xor_sync(0xffffffffu, s, o);
                ss += __shfl_xor_sync(0xffffffffu, ss, o);
            }
            float mean = s * (1.0f / 128.0f);
            float rstd = rsqrtf(ss * (1.0f / 128.0f) - mean * mean + 1e-5f);
            #pragma unroll
            for (int u = 0; u < 4; u++) {
                int c = lane + 32 * u;
                out[((size_t)bn * KK + r) * HH + c] = (v[u] - mean) * rstd * lng[c] + lnb[c];
            }
        }
    }
}

// FFN + LN2 + mask_V. 16 rows per CTA, 256 threads.
__global__ void __launch_bounds__(256, 1)
ffn_kernel(const float* __restrict__ Win, const float* __restrict__ bin,
           const float* __restrict__ Wout, const float* __restrict__ bout,
           const float* __restrict__ lng, const float* __restrict__ lnb,
           const float* __restrict__ maskV,
           float* __restrict__ out)
{
    __shared__ float sX[16 * 128];
    __shared__ float sH[16 * 512];
    const int tid  = threadIdx.x;
    const int row0 = blockIdx.x * 16;

    for (int idx = tid; idx < 16 * 128; idx += 256)
        sX[idx] = g_hV1[(size_t)row0 * 128 + idx];
    __syncthreads();

    // hidden: 512 cols, 2 adjacent per thread, 16 rows
    {
        const int j0 = tid * 2;
        float acc[16][2];
        #pragma unroll
        for (int r = 0; r < 16; r++) { acc[r][0] = bin[j0]; acc[r][1] = bin[j0 + 1]; }
        #pragma unroll 2
        for (int i = 0; i < 128; i++) {
            float2 w = *reinterpret_cast<const float2*>(Win + i * FFD + j0);
            #pragma unroll
            for (int r = 0; r < 16; r++) {
                float a = sX[r * 128 + i];
                acc[r][0] = fmaf(a, w.x, acc[r][0]);
                acc[r][1] = fmaf(a, w.y, acc[r][1]);
            }
        }
        #pragma unroll
        for (int r = 0; r < 16; r++) {
            sH[r * FFD + j0]     = gelu_exact(acc[r][0]);
            sH[r * FFD + j0 + 1] = gelu_exact(acc[r][1]);
        }
    }
    __syncthreads();

    // output projection: col = tid&127, 8 rows per thread
    {
        const int j = tid & 127, rh = tid >> 7;
        float acc[8];
        #pragma unroll
        for (int r = 0; r < 8; r++) acc[r] = bout[j];
        #pragma unroll 2
        for (int i = 0; i < FFD; i++) {
            float w = Wout[i * 128 + j];
            #pragma unroll
            for (int r = 0; r < 8; r++)
                acc[r] = fmaf(sH[(rh * 8 + r) * FFD + i], w, acc[r]);
        }
        #pragma unroll
        for (int r = 0; r < 8; r++)
            sX[(rh * 8 + r) * 128 + j] += acc[r];   // residual in place
    }
    __syncthreads();

    // LN2 per row + mask_V
    int w = tid >> 5, lane = tid & 31;
    for (int r = w; r < 16; r += 8) {
        float v[4];
        #pragma unroll
        for (int u = 0; u < 4; u++) v[u] = sX[r * 128 + lane + 32 * u];
        float s  = v[0] + v[1] + v[2] + v[3];
        float ss = v[0]*v[0] + v[1]*v[1] + v[2]*v[2] + v[3]*v[3];
        #pragma unroll
        for (int o = 16; o; o >>= 1) {
            s  += __shfl_xor_sync(0xffffffffu, s, o);
            ss += __shfl_xor_sync(0xffffffffu, ss, o);
        }
        float mean = s * (1.0f / 128.0f);
        float rstd = rsqrtf(ss * (1.0f / 128.0f) - mean * mean + 1e-5f);
        float mk = maskV[row0 + r];
        #pragma unroll
        for (int u = 0; u < 4; u++) {
            int c = lane + 32 * u;
            out[((size_t)row0 + r) * 128 + c] = mk * ((v[u] - mean) * rstd * lng[c] + lnb[c]);
        }
    }
}

extern "C" void kernel_launch(void* const* d_in, const int* in_sizes, int n_in,
                              void* d_out, int out_size)
{
    const float* hV    = (const float*)d_in[0];
    const float* hE    = (const float*)d_in[1];
    const void*  Eidx  = d_in[2];
    const float* maskV = (const float*)d_in[3];
    const float* maskA = (const float*)d_in[4];
    const float* W1w  = (const float*)d_in[5],  *W1b  = (const float*)d_in[6];
    const float* W2w  = (const float*)d_in[7],  *W2b  = (const float*)d_in[8];
    const float* W3w  = (const float*)d_in[9],  *W3b  = (const float*)d_in[10];
    const float* W11w = (const float*)d_in[11], *W11b = (const float*)d_in[12];
    const float* W12w = (const float*)d_in[13], *W12b = (const float*)d_in[14];
    const float* W13w = (const float*)d_in[15], *W13b = (const float*)d_in[16];
    const float* Winw = (const float*)d_in[17], *Winb = (const float*)d_in[18];
    const float* Woutw= (const float*)d_in[19], *Woutb= (const float*)d_in[20];
    const float* ln1g = (const float*)d_in[21], *ln1b = (const float*)d_in[22];
    const float* ln2g = (const float*)d_in[23], *ln2b = (const float*)d_in[24];
    const float* ln3g = (const float*)d_in[25], *ln3b = (const float*)d_in[26];

    float* out_hV = (float*)d_out;
    float* out_hE = out_hV + (size_t)BN * HH;

    cudaFuncSetAttribute(msg_kernel<false>, cudaFuncAttributeMaxDynamicSharedMemorySize, SMEM_MSG_BYTES);
    cudaFuncSetAttribute(msg_kernel<true>,  cudaFuncAttributeMaxDynamicSharedMemorySize, SMEM_MSG_BYTES);

    // 0) detect E_idx dtype (int32 vs int64) from data pattern
    detect_idx_kernel<<<1, 1>>>((const int*)Eidx);

    // 1) node message + LN1 -> g_hV1
    msg_kernel<false><<<BN, 256, SMEM_MSG_BYTES>>>(
        hV, hE, Eidx, maskA, W1w, W1b, W2w, W2b, W3w, W3b, ln1g, ln1b, nullptr);

    // 2) FFN + LN2 + mask_V -> d_out part 1 (h_Vn)
    ffn_kernel<<<BN / 16, 256>>>(Winw, Winb, Woutw, Woutb, ln2g, ln2b, maskV, out_hV);

    // 3) edge message (uses updated h_Vn) + LN3 -> d_out part 2 (h_En)
    msg_kernel<true><<<BN, 256, SMEM_MSG_BYTES>>>(
        out_hV, hE, Eidx, maskA, W11w, W11b, W12w, W12b, W13w, W13b, ln3g, ln3b, out_hE);

    (void)in_sizes; (void)n_in; (void)out_size;
}

// round 3
// speedup vs baseline: 1.4904x; 1.4904x over previous
#include <cuda_runtime.h>

#define BB  2
#define NN  1024
#define KK  48
#define HH  128
#define FFD 512
#define BN  (BB*NN)
#define LDT 50   // padded transpose stride (even, for LDS.64 row pairs)

// scratch: h_V after node-message + LN1
__device__ float g_hV1[BN*HH];
// E_idx dtype flag: 1 if int64, 0 if int32
__device__ int g_idx64;

__device__ __forceinline__ float gelu_exact(float x) {
    return 0.5f * x * (1.0f + erff(x * 0.70710678118654752f));
}

__global__ void detect_idx_kernel(const int* __restrict__ e32) {
    int all0 = 1;
    #pragma unroll
    for (int i = 1; i < 96; i += 2) all0 &= (e32[i] == 0);
    g_idx64 = all0;
}

__device__ __forceinline__ int load_nbidx(const void* Eidx, int is64, long long pos) {
    int v;
    if (is64) v = (int)((const long long*)Eidx)[pos];
    else      v = ((const int*)Eidx)[pos];
    v = v < 0 ? 0 : (v >= NN ? NN - 1 : v);
    return v;
}

// ---- packed f32x2 helpers ----
typedef unsigned long long ull;
__device__ __forceinline__ ull pack2(float x, float y) {
    ull r; asm("mov.b64 %0, {%1, %2};" : "=l"(r) : "f"(x), "f"(y)); return r;
}
__device__ __forceinline__ void unpack2(ull v, float& x, float& y) {
    asm("mov.b64 {%0, %1}, %2;" : "=f"(x), "=f"(y) : "l"(v));
}
__device__ __forceinline__ void ffma2(ull& d, ull a, ull b) {
    asm("fma.rn.f32x2 %0, %1, %2, %0;" : "+l"(d) : "l"(a), "l"(b));
}

// GEMM tile with packed rows: A transposed in smem [K][LDT] (rows adjacent),
// W [K][128] in global. This thread: 12 rows (6 packed pairs) x 2 cols.
template<int K>
__device__ __forceinline__ void gemm_f32x2(const float* sA,
                                           const float* __restrict__ W,
                                           int r0, int j0, ull acc[6][2]) {
    #pragma unroll 2
    for (int i = 0; i < K; i++) {
        float2 w = *reinterpret_cast<const float2*>(W + i * HH + j0);
        ull w0 = pack2(w.x, w.x);
        ull w1 = pack2(w.y, w.y);
        const ull* ap = reinterpret_cast<const ull*>(sA + i * LDT + r0);
        #pragma unroll
        for (int rp = 0; rp < 6; rp++) {
            ull a = ap[rp];
            ffma2(acc[rp][0], a, w0);
            ffma2(acc[rp][1], a, w1);
        }
    }
}

// smem layout (floats). sX2 aliases sE (dead after GEMM1).
// sV region is reused after GEMM1 for epilogue buffers (sP / row-major LN3 buf).
#define S_E   0
#define S_V   (HH*LDT)          // 6400
#define S_X1  (2*HH*LDT)        // 12800
#define S_X2  S_E
#define S_C   (3*HH*LDT)        // 19200
#define S_CW  (S_C + HH)        // 19328
#define S_SCR (S_CW + HH)       // 19456 (256-float scratch)
#define SMEM_MSG_FLOATS (S_SCR + 256)
#define SMEM_MSG_BYTES  (SMEM_MSG_FLOATS * 4)

// EDGE=false: node message -> masked sum -> LN1(h_V+dh) -> g_hV1
// EDGE=true : edge message -> LN3(h_E+me) -> out
template<bool EDGE>
__global__ void __launch_bounds__(256, 2)
msg_kernel(const float* __restrict__ hVsrc,
           const float* __restrict__ hE,
           const void* __restrict__ Eidx,
           const float* __restrict__ maskA,
           const float* __restrict__ Wa, const float* __restrict__ ba,
           const float* __restrict__ Wb, const float* __restrict__ bb,
           const float* __restrict__ Wc, const float* __restrict__ bc,
           const float* __restrict__ lng, const float* __restrict__ lnb,
           float* __restrict__ out)
{
    extern __shared__ float sm[];
    const int tid = threadIdx.x;
    const int bn  = blockIdx.x;
    const int b   = bn / NN;
    const int is64 = g_idx64;

    const float* center = hVsrc + (size_t)bn * HH;
    const float* hErow  = hE + (size_t)bn * KK * HH;

    // ---- gather (transposed [feature][row]) + center ----
    {
        int j  = tid & 127;
        int rb = tid >> 7;
        if (rb == 0) sm[S_C + j] = center[j];
        for (int r = rb; r < KK; r += 2) {
            int nb = load_nbidx(Eidx, is64, (long long)bn * KK + r);
            sm[S_E + j * LDT + r] = hErow[r * HH + j];
            sm[S_V + j * LDT + r] = hVsrc[((size_t)b * NN + nb) * HH + j];
        }
    }
    __syncthreads();

    // ---- precompute sCW[j] = ba[j] + center . Wa_top[:,j] ----
    {
        int j = tid & 127, half = tid >> 7;
        float p = 0.f;
        const float* wt = Wa + (half * 64) * HH + j;
        const float* c  = sm + S_C + half * 64;
        #pragma unroll 8
        for (int i = 0; i < 64; i++) p = fmaf(c[i], wt[i * HH], p);
        sm[S_SCR + tid] = p;
        __syncthreads();
        if (tid < HH) sm[S_CW + tid] = ba[tid] + sm[S_SCR + tid] + sm[S_SCR + HH + tid];
        __syncthreads();
    }

    const int q  = tid >> 6;
    const int r0 = q * 12;
    const int j0 = (tid & 63) * 2;
    ull acc[6][2];

    // ---- GEMM1: E-part + V-part (K=128 each), init with dedup'd center term ----
    {
        float cw0 = sm[S_CW + j0], cw1 = sm[S_CW + j0 + 1];
        #pragma unroll
        for (int rp = 0; rp < 6; rp++) { acc[rp][0] = pack2(cw0, cw0); acc[rp][1] = pack2(cw1, cw1); }
    }
    gemm_f32x2<HH>(sm + S_E, Wa + 128 * HH, r0, j0, acc);
    gemm_f32x2<HH>(sm + S_V, Wa + 256 * HH, r0, j0, acc);
    #pragma unroll
    for (int rp = 0; rp < 6; rp++) {
        #pragma unroll
        for (int c = 0; c < 2; c++) {
            float x, y; unpack2(acc[rp][c], x, y);
            float2 g = make_float2(gelu_exact(x), gelu_exact(y));
            *reinterpret_cast<float2*>(sm + S_X1 + (j0 + c) * LDT + r0 + 2 * rp) = g;
        }
    }
    __syncthreads();

    // ---- GEMM2 (K=128) + gelu -> sX2 (aliases sE) ----
    {
        float b0 = bb[j0], b1 = bb[j0 + 1];
        #pragma unroll
        for (int rp = 0; rp < 6; rp++) { acc[rp][0] = pack2(b0, b0); acc[rp][1] = pack2(b1, b1); }
    }
    gemm_f32x2<HH>(sm + S_X1, Wb, r0, j0, acc);
    #pragma unroll
    for (int rp = 0; rp < 6; rp++) {
        #pragma unroll
        for (int c = 0; c < 2; c++) {
            float x, y; unpack2(acc[rp][c], x, y);
            float2 g = make_float2(gelu_exact(x), gelu_exact(y));
            *reinterpret_cast<float2*>(sm + S_X2 + (j0 + c) * LDT + r0 + 2 * rp) = g;
        }
    }
    __syncthreads();

    // ---- GEMM3 (K=128) ----
    {
        float b0 = bc[j0], b1 = bc[j0 + 1];
        #pragma unroll
        for (int rp = 0; rp < 6; rp++) { acc[rp][0] = pack2(b0, b0); acc[rp][1] = pack2(b1, b1); }
    }
    gemm_f32x2<HH>(sm + S_X2, Wc, r0, j0, acc);

    if (!EDGE) {
        // masked row-sum of this thread's 12 rows
        float s0 = 0.f, s1 = 0.f;
        const float* mrow = maskA + (size_t)bn * KK;
        #pragma unroll
        for (int rp = 0; rp < 6; rp++) {
            float mk0 = mrow[r0 + 2 * rp];
            float mk1 = mrow[r0 + 2 * rp + 1];
            float x, y;
            unpack2(acc[rp][0], x, y); s0 += mk0 * x + mk1 * y;
            unpack2(acc[rp][1], x, y); s1 += mk0 * x + mk1 * y;
        }
        float* sP = sm + S_V;          // sV dead after GEMM1
        __syncthreads();               // ensure all GEMM1 reads of sV done (they are) & visibility
        sP[q * HH + j0]     = s0;
        sP[q * HH + j0 + 1] = s1;
        __syncthreads();

        if (tid < HH) {
            float dh = (sP[tid] + sP[HH + tid] + sP[2 * HH + tid] + sP[3 * HH + tid]) * (1.0f / 48.0f);
            sP[tid] = center[tid] + dh;
        }
        __syncthreads();
        if (tid < 32) {
            float v0 = sP[tid], v1 = sP[tid + 32], v2 = sP[tid + 64], v3 = sP[tid + 96];
            float s  = v0 + v1 + v2 + v3;
            float ss = v0 * v0 + v1 * v1 + v2 * v2 + v3 * v3;
            #pragma unroll
            for (int o = 16; o; o >>= 1) {
                s  += __shfl_xor_sync(0xffffffffu, s, o);
                ss += __shfl_xor_sync(0xffffffffu, ss, o);
            }
            float mean = s * (1.0f / 128.0f);
            float var  = ss * (1.0f / 128.0f) - mean * mean;
            if (tid == 0) { sP[4 * HH] = mean; sP[4 * HH + 1] = rsqrtf(var + 1e-5f); }
        }
        __syncthreads();
        if (tid < HH) {
            float mean = sP[4 * HH], rstd = sP[4 * HH + 1];
            g_hV1[(size_t)bn * HH + tid] = (sP[tid] - mean) * rstd * lng[tid] + lnb[tid];
        }
    } else {
        // store row-major into sV region, then per-row LN3 with h_E residual
        float* sRM = sm + S_V;
        __syncthreads();
        #pragma unroll
        for (int rp = 0; rp < 6; rp++) {
            float a0, b0, a1, b1;
            unpack2(acc[rp][0], a0, b0);   // rows (even, odd), col j0
            unpack2(acc[rp][1], a1, b1);   // rows (even, odd), col j0+1
            *reinterpret_cast<float2*>(sRM + (r0 + 2 * rp)     * HH + j0) = make_float2(a0, a1);
            *reinterpret_cast<float2*>(sRM + (r0 + 2 * rp + 1) * HH + j0) = make_float2(b0, b1);
        }
        __syncthreads();
        int w = tid >> 5, lane = tid & 31;
        for (int r = w; r < KK; r += 8) {
            float v[4];
            #pragma unroll
            for (int u = 0; u < 4; u++) {
                int c = lane + 32 * u;
                v[u] = sRM[r * HH + c] + hErow[r * HH + c];
            }
            float s  = v[0] + v[1] + v[2] + v[3];
            float ss = v[0]*v[0] + v[1]*v[1] + v[2]*v[2] + v[3]*v[3];
            #pragma unroll
            for (int o = 16; o; o >>= 1) {
                s  += __shfl_xor_sync(0xffffffffu, s, o);
                ss += __shfl_xor_sync(0xffffffffu, ss, o);
            }
            float mean = s * (1.0f / 128.0f);
            float rstd = rsqrtf(ss * (1.0f / 128.0f) - mean * mean + 1e-5f);
            #pragma unroll
            for (int u = 0; u < 4; u++) {
                int c = lane + 32 * u;
                out[((size_t)bn * KK + r) * HH + c] = (v[u] - mean) * rstd * lng[c] + lnb[c];
            }
        }
    }
}

// FFN + LN2 + mask_V. 16 rows per CTA, 256 threads.
__global__ void __launch_bounds__(256, 1)
ffn_kernel(const float* __restrict__ Win, const float* __restrict__ bin,
           const float* __restrict__ Wout, const float* __restrict__ bout,
           const float* __restrict__ lng, const float* __restrict__ lnb,
           const float* __restrict__ maskV,
           float* __restrict__ out)
{
    __shared__ float sX[16 * 128];
    __shared__ float sH[16 * 512];
    const int tid  = threadIdx.x;
    const int row0 = blockIdx.x * 16;

    for (int idx = tid; idx < 16 * 128; idx += 256)
        sX[idx] = g_hV1[(size_t)row0 * 128 + idx];
    __syncthreads();

    {
        const int j0 = tid * 2;
        float acc[16][2];
        #pragma unroll
        for (int r = 0; r < 16; r++) { acc[r][0] = bin[j0]; acc[r][1] = bin[j0 + 1]; }
        #pragma unroll 2
        for (int i = 0; i < 128; i++) {
            float2 w = *reinterpret_cast<const float2*>(Win + i * FFD + j0);
            #pragma unroll
            for (int r = 0; r < 16; r++) {
                float a = sX[r * 128 + i];
                acc[r][0] = fmaf(a, w.x, acc[r][0]);
                acc[r][1] = fmaf(a, w.y, acc[r][1]);
            }
        }
        #pragma unroll
        for (int r = 0; r < 16; r++) {
            sH[r * FFD + j0]     = gelu_exact(acc[r][0]);
            sH[r * FFD + j0 + 1] = gelu_exact(acc[r][1]);
        }
    }
    __syncthreads();

    {
        const int j = tid & 127, rh = tid >> 7;
        float acc[8];
        #pragma unroll
        for (int r = 0; r < 8; r++) acc[r] = bout[j];
        #pragma unroll 2
        for (int i = 0; i < FFD; i++) {
            float w = Wout[i * 128 + j];
            #pragma unroll
            for (int r = 0; r < 8; r++)
                acc[r] = fmaf(sH[(rh * 8 + r) * FFD + i], w, acc[r]);
        }
        #pragma unroll
        for (int r = 0; r < 8; r++)
            sX[(rh * 8 + r) * 128 + j] += acc[r];
    }
    __syncthreads();

    int w = tid >> 5, lane = tid & 31;
    for (int r = w; r < 16; r += 8) {
        float v[4];
        #pragma unroll
        for (int u = 0; u < 4; u++) v[u] = sX[r * 128 + lane + 32 * u];
        float s  = v[0] + v[1] + v[2] + v[3];
        float ss = v[0]*v[0] + v[1]*v[1] + v[2]*v[2] + v[3]*v[3];
        #pragma unroll
        for (int o = 16; o; o >>= 1) {
            s  += __shfl_xor_sync(0xffffffffu, s, o);
            ss += __shfl_xor_sync(0xffffffffu, ss, o);
        }
        float mean = s * (1.0f / 128.0f);
        float rstd = rsqrtf(ss * (1.0f / 128.0f) - mean * mean + 1e-5f);
        float mk = maskV[row0 + r];
        #pragma unroll
        for (int u = 0; u < 4; u++) {
            int c = lane + 32 * u;
            out[((size_t)row0 + r) * 128 + c] = mk * ((v[u] - mean) * rstd * lng[c] + lnb[c]);
        }
    }
}

extern "C" void kernel_launch(void* const* d_in, const int* in_sizes, int n_in,
                              void* d_out, int out_size)
{
    const float* hV    = (const float*)d_in[0];
    const float* hE    = (const float*)d_in[1];
    const void*  Eidx  = d_in[2];
    const float* maskV = (const float*)d_in[3];
    const float* maskA = (const float*)d_in[4];
    const float* W1w  = (const float*)d_in[5],  *W1b  = (const float*)d_in[6];
    const float* W2w  = (const float*)d_in[7],  *W2b  = (const float*)d_in[8];
    const float* W3w  = (const float*)d_in[9],  *W3b  = (const float*)d_in[10];
    const float* W11w = (const float*)d_in[11], *W11b = (const float*)d_in[12];
    const float* W12w = (const float*)d_in[13], *W12b = (const float*)d_in[14];
    const float* W13w = (const float*)d_in[15], *W13b = (const float*)d_in[16];
    const float* Winw = (const float*)d_in[17], *Winb = (const float*)d_in[18];
    const float* Woutw= (const float*)d_in[19], *Woutb= (const float*)d_in[20];
    const float* ln1g = (const float*)d_in[21], *ln1b = (const float*)d_in[22];
    const float* ln2g = (const float*)d_in[23], *ln2b = (const float*)d_in[24];
    const float* ln3g = (const float*)d_in[25], *ln3b = (const float*)d_in[26];

    float* out_hV = (float*)d_out;
    float* out_hE = out_hV + (size_t)BN * HH;

    cudaFuncSetAttribute(msg_kernel<false>, cudaFuncAttributeMaxDynamicSharedMemorySize, SMEM_MSG_BYTES);
    cudaFuncSetAttribute(msg_kernel<true>,  cudaFuncAttributeMaxDynamicSharedMemorySize, SMEM_MSG_BYTES);

    detect_idx_kernel<<<1, 1>>>((const int*)Eidx);

    msg_kernel<false><<<BN, 256, SMEM_MSG_BYTES>>>(
        hV, hE, Eidx, maskA, W1w, W1b, W2w, W2b, W3w, W3b, ln1g, ln1b, nullptr);

    ffn_kernel<<<BN / 16, 256>>>(Winw, Winb, Woutw, Woutb, ln2g, ln2b, maskV, out_hV);

    msg_kernel<true><<<BN, 256, SMEM_MSG_BYTES>>>(
        out_hV, hE, Eidx, maskA, W11w, W11b, W12w, W12b, W13w, W13b, ln3g, ln3b, out_hE);

    (void)in_sizes; (void)n_in; (void)out_size;
}

// round 5
// speedup vs baseline: 2.0106x; 1.3491x over previous
#include <cuda_runtime.h>
#include <cuda_bf16.h>
#include <cstdint>

#define BB  2
#define NN  1024
#define KK  48
#define HH  128
#define FFD 512
#define BN  (BB*NN)
#define NEDGE (BN*KK)          // 98304
#define MT  128                // edge rows per CTA
#define NCTA (NEDGE/MT)        // 768

// smem layout (bytes): tiles are 128x64 bf16 = 16KB each, 128B rows (SW128)
#define TILE_B  16384
#define SM_B    1024                       // 4 tiles: [hi_k0][hi_k1][lo_k0][lo_k1]
#define SM_A2   (SM_B  + 4*TILE_B)         // 66560 : 4 tiles
#define SM_A3   (SM_A2 + 4*TILE_B)         // 132096: 4 tiles (first 2 also GEMM1 stream buf)
#define SM_TOTAL (SM_A3 + 4*TILE_B)        // 197632

// weight-transpose offsets (elements) within one msg's region
#define WOFF_G1 0
#define WOFF_G2 (384*HH)
#define WOFF_G3 (WOFF_G2 + 128*HH)
#define WMSG    (WOFF_G3 + 128*HH)

__device__ float g_hV1[BN*HH];
__device__ float g_m[(size_t)NEDGE*HH];
__device__ __align__(16) __nv_bfloat16 g_WThi[2*WMSG];
__device__ __align__(16) __nv_bfloat16 g_WTlo[2*WMSG];
__device__ int g_idx64;

__device__ __forceinline__ float gelu_exact(float x) {
    return 0.5f * x * (1.0f + erff(x * 0.70710678118654752f));
}

__global__ void detect_idx_kernel(const int* __restrict__ e32) {
    int all0 = 1;
    #pragma unroll
    for (int i = 1; i < 96; i += 2) all0 &= (e32[i] == 0);
    g_idx64 = all0;
}

__device__ __forceinline__ int load_nbidx(const void* Eidx, int is64, long long pos) {
    int v;
    if (is64) v = (int)((const long long*)Eidx)[pos];
    else      v = ((const int*)Eidx)[pos];
    v = v < 0 ? 0 : (v >= NN ? NN - 1 : v);
    return v;
}

// W [K,128] fp32 -> WT [128,K] bf16 hi/lo
__global__ void prep_w(const float* __restrict__ W, int K,
                       __nv_bfloat16* __restrict__ dh, __nv_bfloat16* __restrict__ dl) {
    int id = blockIdx.x * blockDim.x + threadIdx.x;
    if (id >= K * HH) return;
    int k = id >> 7, n = id & 127;
    float x = W[id];
    __nv_bfloat16 h = __float2bfloat16(x);
    float rem = x - __bfloat162float(h);
    dh[(size_t)n * K + k] = h;
    dl[(size_t)n * K + k] = __float2bfloat16(rem);
}

// ---------------- PTX helpers (target-generic: ldmatrix + mma.sync) ----------------
__device__ __forceinline__ uint32_t smem_u32(const void* p) {
    uint32_t a;
    asm("{ .reg .u64 t; cvta.to.shared.u64 t, %1; cvt.u32.u64 %0, t; }" : "=r"(a) : "l"(p));
    return a;
}
__device__ __forceinline__ uint32_t sw128(uint32_t off) {
    return off ^ ((off >> 3) & 0x70);
}
__device__ __forceinline__ void ldsm4(uint32_t* r, uint32_t addr) {
    asm volatile("ldmatrix.sync.aligned.m8n8.x4.shared.b16 {%0,%1,%2,%3}, [%4];"
        : "=r"(r[0]), "=r"(r[1]), "=r"(r[2]), "=r"(r[3]) : "r"(addr));
}
__device__ __forceinline__ void mma16816(float* d, const uint32_t* a, const uint32_t* b) {
    asm volatile("mma.sync.aligned.m16n8k16.row.col.f32.bf16.bf16.f32 "
        "{%0,%1,%2,%3}, {%4,%5,%6,%7}, {%8,%9}, {%0,%1,%2,%3};"
        : "+f"(d[0]), "+f"(d[1]), "+f"(d[2]), "+f"(d[3])
        : "r"(a[0]), "r"(a[1]), "r"(a[2]), "r"(a[3]), "r"(b[0]), "r"(b[1]));
}
// A fragment m16k16 from tile [row][64k] (128B rows, SW128)
__device__ __forceinline__ void ldsmA(uint32_t* r, uint32_t tbase, int mrow, int klo, int lane) {
    int q = lane >> 3;
    int row = mrow + (lane & 7) + 8 * (q & 1);
    int kk  = klo + 8 * (q >> 1);
    ldsm4(r, tbase + sw128((uint32_t)(row * 128 + kk * 2)));
}
// B fragments for 2 adjacent n-tiles: r[0..1]=ntile@nrow0 (klo,khi), r[2..3]=ntile@nrow0+8
__device__ __forceinline__ void ldsmB(uint32_t* r, uint32_t tbase, int nrow0, int klo, int lane) {
    int q = lane >> 3;
    int row = nrow0 + (lane & 7) + 8 * (q >> 1);
    int kk  = klo + 8 * (q & 1);
    ldsm4(r, tbase + sw128((uint32_t)(row * 128 + kk * 2)));
}

__device__ __forceinline__ uint32_t pack_bf2(__nv_bfloat16 a, __nv_bfloat16 b) {
    return (uint32_t)__bfloat16_as_ushort(a) | ((uint32_t)__bfloat16_as_ushort(b) << 16);
}
__device__ __forceinline__ void split2(float x, float y, uint32_t& hi, uint32_t& lo) {
    __nv_bfloat16 hx = __float2bfloat16(x), hy = __float2bfloat16(y);
    __nv_bfloat16 lx = __float2bfloat16(x - __bfloat162float(hx));
    __nv_bfloat16 ly = __float2bfloat16(y - __bfloat162float(hy));
    hi = pack_bf2(hx, hy);
    lo = pack_bf2(lx, ly);
}

// one 64-wide K chunk of 3-term-split MMA into acc[2][8][4]
__device__ __forceinline__ void mma_chunk(uint32_t aHi, uint32_t aLo,
                                          uint32_t bHi, uint32_t bLo,
                                          int m0, int n0, int lane,
                                          float acc[2][8][4]) {
    #pragma unroll
    for (int ks = 0; ks < 4; ks++) {
        int klo = ks * 16;
        uint32_t Ah[2][4], Al[2][4];
        ldsmA(Ah[0], aHi, m0,      klo, lane);
        ldsmA(Ah[1], aHi, m0 + 16, klo, lane);
        ldsmA(Al[0], aLo, m0,      klo, lane);
        ldsmA(Al[1], aLo, m0 + 16, klo, lane);
        #pragma unroll
        for (int p = 0; p < 4; p++) {            // n-tile pairs
            uint32_t Bh[4], Bl[4];
            ldsmB(Bh, bHi, n0 + p * 16, klo, lane);
            ldsmB(Bl, bLo, n0 + p * 16, klo, lane);
            #pragma unroll
            for (int mt = 0; mt < 2; mt++) {
                #pragma unroll
                for (int s = 0; s < 2; s++) {    // which n-tile of the pair
                    int nt = p * 2 + s;
                    mma16816(acc[mt][nt], Ah[mt], &Bh[s * 2]);
                    mma16816(acc[mt][nt], Ah[mt], &Bl[s * 2]);
                    mma16816(acc[mt][nt], Al[mt], &Bh[s * 2]);
                }
            }
        }
    }
}

// ---------------- fused GEMM-chain message kernel ----------------
template<bool EDGE>
__global__ void __launch_bounds__(256)
gemm_msg_kernel(const float* __restrict__ hVsrc,
                const float* __restrict__ hE,
                const void*  __restrict__ Eidx,
                const float* __restrict__ maskA,
                const float* __restrict__ ba, const float* __restrict__ bb,
                const float* __restrict__ bc,
                int wbase,
                const float* __restrict__ lng, const float* __restrict__ lnb,
                float* __restrict__ out)
{
    extern __shared__ uint8_t smem8[];
    const int tid  = threadIdx.x;
    const int wid  = tid >> 5;
    const int lane = tid & 31;
    const int e0   = blockIdx.x * MT;
    const int is64 = g_idx64;
    const uint32_t sbase = smem_u32(smem8);

    const int m0 = (wid & 3) * 32;   // warp's 32 output rows
    const int n0 = (wid >> 2) * 64;  // warp's 64 output cols

    const __nv_bfloat16* WTh = g_WThi + wbase;
    const __nv_bfloat16* WTl = g_WTlo + wbase;

    float acc[2][8][4];

    auto zero_acc = [&]() {
        #pragma unroll
        for (int mt = 0; mt < 2; mt++)
            #pragma unroll
            for (int nt = 0; nt < 8; nt++)
                #pragma unroll
                for (int i = 0; i < 4; i++) acc[mt][nt][i] = 0.f;
    };

    // fill B chunk (weights) into slot kt: hi->SM_B+kt*T, lo->SM_B+(2+kt)*T
    auto fill_B = [&](int woff, int Klen, int kbase, int kt) {
        const __nv_bfloat16* bh = WTh + woff;
        const __nv_bfloat16* bl = WTl + woff;
        int u = tid & 7;
        uint8_t* dh = smem8 + SM_B + kt * TILE_B;
        uint8_t* dl = smem8 + SM_B + (2 + kt) * TILE_B;
        for (int n = tid >> 3; n < 128; n += 32) {
            uint4 vh = ((const uint4*)(bh + (size_t)n * Klen + kbase))[u];
            uint4 vl = ((const uint4*)(bl + (size_t)n * Klen + kbase))[u];
            uint32_t sw = sw128((uint32_t)n * 128 + u * 16);
            *(uint4*)(dh + sw) = vh;
            *(uint4*)(dl + sw) = vl;
        }
    };

    // epilogue: bias + gelu + split -> dst tiles (4-tile group at dstOff)
    auto epi_act = [&](const float* __restrict__ bias, uint32_t dstOff) {
        #pragma unroll
        for (int mt = 0; mt < 2; mt++) {
            #pragma unroll
            for (int nt = 0; nt < 8; nt++) {
                int row = m0 + mt * 16 + (lane >> 2);
                int c0  = n0 + nt * 8 + 2 * (lane & 3);
                float b0v = bias[c0], b1v = bias[c0 + 1];
                int kt = c0 >> 6, kk = c0 & 63;
                uint8_t* dH = smem8 + dstOff + kt * TILE_B;
                uint8_t* dL = smem8 + dstOff + (2 + kt) * TILE_B;
                float x0 = gelu_exact(acc[mt][nt][0] + b0v);
                float y0 = gelu_exact(acc[mt][nt][1] + b1v);
                float x1 = gelu_exact(acc[mt][nt][2] + b0v);
                float y1 = gelu_exact(acc[mt][nt][3] + b1v);
                uint32_t hi, lo;
                split2(x0, y0, hi, lo);
                uint32_t sw = sw128((uint32_t)(row * 128 + kk * 2));
                *(uint32_t*)(dH + sw) = hi; *(uint32_t*)(dL + sw) = lo;
                split2(x1, y1, hi, lo);
                sw = sw128((uint32_t)((row + 8) * 128 + kk * 2));
                *(uint32_t*)(dH + sw) = hi; *(uint32_t*)(dL + sw) = lo;
            }
        }
    };

    // ========== GEMM1: K=384, 6 streamed 64-chunks (A buf = first 2 tiles of A3) ==========
    zero_acc();
    for (int ch = 0; ch < 6; ch++) {
        // fill A chunk: 128 rows x 64 fp32 -> split bf16 swizzled
        {
            int c4 = tid & 15;
            uint8_t* aH = smem8 + SM_A3;
            uint8_t* aL = smem8 + SM_A3 + TILE_B;
            for (int r = tid >> 4; r < MT; r += 16) {
                int e = e0 + r;
                const float* src;
                if (ch < 2)      { int n = e / KK; src = hVsrc + (size_t)n * HH + ch * 64; }
                else if (ch < 4) { src = hE + (size_t)e * HH + (ch - 2) * 64; }
                else {
                    int b  = e / (KK * NN);
                    int nb = load_nbidx(Eidx, is64, e);
                    src = hVsrc + ((size_t)b * NN + nb) * HH + (ch - 4) * 64;
                }
                float4 v = *((const float4*)src + c4);
                uint32_t h01, l01, h23, l23;
                split2(v.x, v.y, h01, l01);
                split2(v.z, v.w, h23, l23);
                uint32_t sw = sw128((uint32_t)r * 128 + c4 * 8);
                *(uint2*)(aH + sw) = make_uint2(h01, h23);
                *(uint2*)(aL + sw) = make_uint2(l01, l23);
            }
        }
        fill_B(WOFF_G1, 384, ch * 64, 0);
        __syncthreads();
        mma_chunk(sbase + SM_A3, sbase + SM_A3 + TILE_B,
                  sbase + SM_B,  sbase + SM_B + 2 * TILE_B, m0, n0, lane, acc);
        __syncthreads();
    }
    epi_act(ba, SM_A2);
    __syncthreads();

    // ========== GEMM2: K=128, A = A2 tiles ==========
    fill_B(WOFF_G2, 128, 0, 0);
    fill_B(WOFF_G2, 128, 64, 1);
    zero_acc();
    __syncthreads();
    #pragma unroll
    for (int kt = 0; kt < 2; kt++)
        mma_chunk(sbase + SM_A2 + kt * TILE_B, sbase + SM_A2 + (2 + kt) * TILE_B,
                  sbase + SM_B  + kt * TILE_B, sbase + SM_B  + (2 + kt) * TILE_B,
                  m0, n0, lane, acc);
    __syncthreads();
    epi_act(bb, SM_A3);
    __syncthreads();

    // ========== GEMM3: K=128, A = A3 tiles ==========
    fill_B(WOFF_G3, 128, 0, 0);
    fill_B(WOFF_G3, 128, 64, 1);
    zero_acc();
    __syncthreads();
    #pragma unroll
    for (int kt = 0; kt < 2; kt++)
        mma_chunk(sbase + SM_A3 + kt * TILE_B, sbase + SM_A3 + (2 + kt) * TILE_B,
                  sbase + SM_B  + kt * TILE_B, sbase + SM_B  + (2 + kt) * TILE_B,
                  m0, n0, lane, acc);
    __syncthreads();   // B dead now; reuse as fp32 staging

    // ---- final epilogue: bias (+mask) -> stage fp32 in SM_B ----
    float* sOut = (float*)(smem8 + SM_B);   // 128x128 f32 = 64KB
    {
        #pragma unroll
        for (int mt = 0; mt < 2; mt++) {
            int row = m0 + mt * 16 + (lane >> 2);
            float mk0 = 1.f, mk1 = 1.f;
            if (!EDGE) { mk0 = maskA[e0 + row]; mk1 = maskA[e0 + row + 8]; }
            #pragma unroll
            for (int nt = 0; nt < 8; nt++) {
                int c0 = n0 + nt * 8 + 2 * (lane & 3);
                float b0v = bc[c0], b1v = bc[c0 + 1];
                sOut[row * 128 + c0]           = (acc[mt][nt][0] + b0v) * mk0;
                sOut[row * 128 + c0 + 1]       = (acc[mt][nt][1] + b1v) * mk0;
                sOut[(row + 8) * 128 + c0]     = (acc[mt][nt][2] + b0v) * mk1;
                sOut[(row + 8) * 128 + c0 + 1] = (acc[mt][nt][3] + b1v) * mk1;
            }
        }
        __syncthreads();
    }

    if (!EDGE) {
        float4* d4 = (float4*)(g_m + (size_t)e0 * HH);
        const float4* s4 = (const float4*)sOut;
        #pragma unroll
        for (int p = 0; p < 16; p++) d4[tid + p * 256] = s4[tid + p * 256];
    } else {
        for (int r = wid; r < MT; r += 8) {
            const float* her = hE + (size_t)(e0 + r) * HH;
            float v[4];
            #pragma unroll
            for (int u = 0; u < 4; u++) {
                int c = lane + 32 * u;
                v[u] = sOut[r * 128 + c] + her[c];
            }
            float s  = v[0] + v[1] + v[2] + v[3];
            float ss = v[0]*v[0] + v[1]*v[1] + v[2]*v[2] + v[3]*v[3];
            #pragma unroll
            for (int o = 16; o; o >>= 1) {
                s  += __shfl_xor_sync(0xffffffffu, s, o);
                ss += __shfl_xor_sync(0xffffffffu, ss, o);
            }
            float mean = s * (1.0f / 128.0f);
            float rstd = rsqrtf(ss * (1.0f / 128.0f) - mean * mean + 1e-5f);
            #pragma unroll
            for (int u = 0; u < 4; u++) {
                int c = lane + 32 * u;
                out[(size_t)(e0 + r) * HH + c] = (v[u] - mean) * rstd * lng[c] + lnb[c];
            }
        }
    }
}

// ---------------- node reduction + LN1 ----------------
__global__ void __launch_bounds__(128)
reduce_ln1(const float* __restrict__ hV,
           const float* __restrict__ lng, const float* __restrict__ lnb)
{
    int bn = blockIdx.x, j = threadIdx.x;
    int w = j >> 5, lane = j & 31;
    float s = 0.f;
    const float* mp = g_m + (size_t)bn * KK * HH + j;
    #pragma unroll 8
    for (int k = 0; k < KK; k++) s += mp[(size_t)k * HH];
    float v = hV[(size_t)bn * HH + j] + s * (1.0f / 48.0f);

    __shared__ float rs[4], rq[4];
    float a = v, q = v * v;
    #pragma unroll
    for (int o = 16; o; o >>= 1) {
        a += __shfl_xor_sync(0xffffffffu, a, o);
        q += __shfl_xor_sync(0xffffffffu, q, o);
    }
    if (lane == 0) { rs[w] = a; rq[w] = q; }
    __syncthreads();
    float S = rs[0] + rs[1] + rs[2] + rs[3];
    float Q = rq[0] + rq[1] + rq[2] + rq[3];
    float mean = S * (1.0f / 128.0f);
    float rstd = rsqrtf(Q * (1.0f / 128.0f) - mean * mean + 1e-5f);
    g_hV1[(size_t)bn * HH + j] = (v - mean) * rstd * lng[j] + lnb[j];
}

// ---------------- FFN + LN2 + mask_V (fp32) ----------------
__global__ void __launch_bounds__(256, 1)
ffn_kernel(const float* __restrict__ Win, const float* __restrict__ bin,
           const float* __restrict__ Wout, const float* __restrict__ bout,
           const float* __restrict__ lng, const float* __restrict__ lnb,
           const float* __restrict__ maskV,
           float* __restrict__ out)
{
    __shared__ float sX[16 * 128];
    __shared__ float sH[16 * 512];
    const int tid  = threadIdx.x;
    const int row0 = blockIdx.x * 16;

    for (int idx = tid; idx < 16 * 128; idx += 256)
        sX[idx] = g_hV1[(size_t)row0 * 128 + idx];
    __syncthreads();

    {
        const int j0 = tid * 2;
        float acc[16][2];
        #pragma unroll
        for (int r = 0; r < 16; r++) { acc[r][0] = bin[j0]; acc[r][1] = bin[j0 + 1]; }
        #pragma unroll 2
        for (int i = 0; i < 128; i++) {
            float2 w = *reinterpret_cast<const float2*>(Win + i * FFD + j0);
            #pragma unroll
            for (int r = 0; r < 16; r++) {
                float a = sX[r * 128 + i];
                acc[r][0] = fmaf(a, w.x, acc[r][0]);
                acc[r][1] = fmaf(a, w.y, acc[r][1]);
            }
        }
        #pragma unroll
        for (int r = 0; r < 16; r++) {
            sH[r * FFD + j0]     = gelu_exact(acc[r][0]);
            sH[r * FFD + j0 + 1] = gelu_exact(acc[r][1]);
        }
    }
    __syncthreads();

    {
        const int j = tid & 127, rh = tid >> 7;
        float acc[8];
        #pragma unroll
        for (int r = 0; r < 8; r++) acc[r] = bout[j];
        #pragma unroll 2
        for (int i = 0; i < FFD; i++) {
            float w = Wout[i * 128 + j];
            #pragma unroll
            for (int r = 0; r < 8; r++)
                acc[r] = fmaf(sH[(rh * 8 + r) * FFD + i], w, acc[r]);
        }
        #pragma unroll
        for (int r = 0; r < 8; r++)
            sX[(rh * 8 + r) * 128 + j] += acc[r];
    }
    __syncthreads();

    int w = tid >> 5, lane = tid & 31;
    for (int r = w; r < 16; r += 8) {
        float v[4];
        #pragma unroll
        for (int u = 0; u < 4; u++) v[u] = sX[r * 128 + lane + 32 * u];
        float s  = v[0] + v[1] + v[2] + v[3];
        float ss = v[0]*v[0] + v[1]*v[1] + v[2]*v[2] + v[3]*v[3];
        #pragma unroll
        for (int o = 16; o; o >>= 1) {
            s  += __shfl_xor_sync(0xffffffffu, s, o);
            ss += __shfl_xor_sync(0xffffffffu, ss, o);
        }
        float mean = s * (1.0f / 128.0f);
        float rstd = rsqrtf(ss * (1.0f / 128.0f) - mean * mean + 1e-5f);
        float mk = maskV[row0 + r];
        #pragma unroll
        for (int u = 0; u < 4; u++) {
            int c = lane + 32 * u;
            out[((size_t)row0 + r) * 128 + c] = mk * ((v[u] - mean) * rstd * lng[c] + lnb[c]);
        }
    }
}

extern "C" void kernel_launch(void* const* d_in, const int* in_sizes, int n_in,
                              void* d_out, int out_size)
{
    const float* hV    = (const float*)d_in[0];
    const float* hE    = (const float*)d_in[1];
    const void*  Eidx  = d_in[2];
    const float* maskV = (const float*)d_in[3];
    const float* maskA = (const float*)d_in[4];
    const float* W1w  = (const float*)d_in[5],  *W1b  = (const float*)d_in[6];
    const float* W2w  = (const float*)d_in[7],  *W2b  = (const float*)d_in[8];
    const float* W3w  = (const float*)d_in[9],  *W3b  = (const float*)d_in[10];
    const float* W11w = (const float*)d_in[11], *W11b = (const float*)d_in[12];
    const float* W12w = (const float*)d_in[13], *W12b = (const float*)d_in[14];
    const float* W13w = (const float*)d_in[15], *W13b = (const float*)d_in[16];
    const float* Winw = (const float*)d_in[17], *Winb = (const float*)d_in[18];
    const float* Woutw= (const float*)d_in[19], *Woutb= (const float*)d_in[20];
    const float* ln1g = (const float*)d_in[21], *ln1b = (const float*)d_in[22];
    const float* ln2g = (const float*)d_in[23], *ln2b = (const float*)d_in[24];
    const float* ln3g = (const float*)d_in[25], *ln3b = (const float*)d_in[26];

    float* out_hV = (float*)d_out;
    float* out_hE = out_hV + (size_t)BN * HH;

    cudaFuncSetAttribute(gemm_msg_kernel<false>, cudaFuncAttributeMaxDynamicSharedMemorySize, SM_TOTAL);
    cudaFuncSetAttribute(gemm_msg_kernel<true>,  cudaFuncAttributeMaxDynamicSharedMemorySize, SM_TOTAL);

    __nv_bfloat16 *wthi = nullptr, *wtlo = nullptr;
    cudaGetSymbolAddress((void**)&wthi, g_WThi);
    cudaGetSymbolAddress((void**)&wtlo, g_WTlo);

    detect_idx_kernel<<<1, 1>>>((const int*)Eidx);

    prep_w<<<(384 * HH + 255) / 256, 256>>>(W1w,  384, wthi + WOFF_G1,        wtlo + WOFF_G1);
    prep_w<<<(128 * HH + 255) / 256, 256>>>(W2w,  128, wthi + WOFF_G2,        wtlo + WOFF_G2);
    prep_w<<<(128 * HH + 255) / 256, 256>>>(W3w,  128, wthi + WOFF_G3,        wtlo + WOFF_G3);
    prep_w<<<(384 * HH + 255) / 256, 256>>>(W11w, 384, wthi + WMSG + WOFF_G1, wtlo + WMSG + WOFF_G1);
    prep_w<<<(128 * HH + 255) / 256, 256>>>(W12w, 128, wthi + WMSG + WOFF_G2, wtlo + WMSG + WOFF_G2);
    prep_w<<<(128 * HH + 255) / 256, 256>>>(W13w, 128, wthi + WMSG + WOFF_G3, wtlo + WMSG + WOFF_G3);

    gemm_msg_kernel<false><<<NCTA, 256, SM_TOTAL>>>(
        hV, hE, Eidx, maskA, W1b, W2b, W3b, 0, nullptr, nullptr, nullptr);

    reduce_ln1<<<BN, 128>>>(hV, ln1g, ln1b);

    ffn_kernel<<<BN / 16, 256>>>(Winw, Winb, Woutw, Woutb, ln2g, ln2b, maskV, out_hV);

    gemm_msg_kernel<true><<<NCTA, 256, SM_TOTAL>>>(
        out_hV, hE, Eidx, maskA, W11b, W12b, W13b, WMSG, ln3g, ln3b, out_hE);

    (void)in_sizes; (void)n_in; (void)out_size;
}